// round 12
// baseline (speedup 1.0000x reference)
#include <cuda_runtime.h>

#define BATCH  8
#define NPTS   4096
#define TPB    64
#define QPT    4
#define QPB    (TPB * QPT)       // 256 queries per block
#define ITILES (NPTS / QPB)      // 16
#define NSPLIT 8                 // target splits
#define CHUNK  (NPTS / NSPLIT)   // 512 targets per block (one 8KB smem tile)
#define NQ     (2 * BATCH * NPTS)            // 65536 queries
#define NBLK   (ITILES * BATCH * 2 * NSPLIT) // 2048 blocks

// bits of -(min d2) per query, signed-int atomicMin.
// .bss zero (= +0.0 bits) is the identity: any negative int wins. No init.
// Finisher re-zeros after reading, restoring state for graph replay.
__device__ __align__(16) int g_minneg[NQ];
__device__ unsigned int      g_count;        // zero-init; finisher resets

// ---- packed f32x2 helpers (Blackwell; PTX-only) ----
__device__ __forceinline__ unsigned long long bcast2(float v) {
    unsigned long long r;
    asm("mov.b64 %0, {%1, %1};" : "=l"(r) : "f"(v));
    return r;
}
__device__ __forceinline__ unsigned long long fma2(unsigned long long a,
                                                   unsigned long long b,
                                                   unsigned long long c) {
    unsigned long long d;
    asm("fma.rn.f32x2 %0, %1, %2, %3;" : "=l"(d) : "l"(a), "l"(b), "l"(c));
    return d;
}
__device__ __forceinline__ void unpack2(unsigned long long v, float& lo, float& hi) {
    asm("mov.b64 {%0, %1}, %2;" : "=f"(lo), "=f"(hi) : "l"(v));
}

// grid (ITILES, BATCH, 2*NSPLIT); z: dir = z&1, split = z>>1.
// Hot path identical to Round 10 (best measured, ~40us). Fused finisher uses
// NO gpu-scope fence: atomic-return values prove L2 commit (release), and the
// last block reads via __ldcv / L1-bypass (acquire). CCTL.IVALL never fires.
__global__ __launch_bounds__(TPB) void chamfer_kernel(
    const float* __restrict__ A, const float* __restrict__ Bp,
    float* __restrict__ out)
{
    const int dir   = blockIdx.z & 1;
    const int split = blockIdx.z >> 1;
    const int b     = blockIdx.y;
    const float* __restrict__ xb = (dir == 0 ? A : Bp) + (size_t)b * NPTS * 3;
    const float* __restrict__ yb = (dir == 0 ? Bp : A) + (size_t)b * NPTS * 3;

    __shared__ __align__(16) float xs[CHUNK], ys[CHUNK], zs[CHUNK], ws[CHUNK];
    __shared__ volatile int s_dummy;          // dependency anchor (never read)

    // ---- load the target tile (once per block) ----
    const int t0 = split * CHUNK;
    #pragma unroll
    for (int k = threadIdx.x; k < CHUNK; k += TPB) {
        const float qx = yb[3 * (t0 + k) + 0];
        const float qy = yb[3 * (t0 + k) + 1];
        const float qz = yb[3 * (t0 + k) + 2];
        xs[k] = qx; ys[k] = qy; zs[k] = qz;
        ws[k] = fmaf(qx, qx, fmaf(qy, qy, qz * qz));
    }

    // ---- load 4 query points, fold -2 into packed broadcasts ----
    const int iBase = blockIdx.x * QPB + threadIdx.x;
    float p2[QPT];
    unsigned long long nx[QPT], ny[QPT], nz[QPT];
    #pragma unroll
    for (int q = 0; q < QPT; q++) {
        const int i = iBase + q * TPB;
        const float px = xb[3 * i + 0];
        const float py = xb[3 * i + 1];
        const float pz = xb[3 * i + 2];
        p2[q] = fmaf(px, px, fmaf(py, py, pz * pz));
        nx[q] = bcast2(-2.0f * px);
        ny[q] = bcast2(-2.0f * py);
        nz[q] = bcast2(-2.0f * pz);
    }

    __syncthreads();

    float m0[QPT], m1[QPT], m2[QPT], m3[QPT];
    #pragma unroll
    for (int q = 0; q < QPT; q++) { m0[q] = m1[q] = m2[q] = m3[q] = 3.0e38f; }

    const ulonglong2* __restrict__ X4 = (const ulonglong2*)xs;
    const ulonglong2* __restrict__ Y4 = (const ulonglong2*)ys;
    const ulonglong2* __restrict__ Z4 = (const ulonglong2*)zs;
    const ulonglong2* __restrict__ W4 = (const ulonglong2*)ws;

    #pragma unroll 4
    for (int j = 0; j < CHUNK / 4; j++) {
        const ulonglong2 xv = X4[j];   // {x0,x1},{x2,x3} packed f32x2 (broadcast)
        const ulonglong2 yv = Y4[j];
        const ulonglong2 zv = Z4[j];
        const ulonglong2 wv = W4[j];

        #pragma unroll
        for (int q = 0; q < QPT; q++) {
            const unsigned long long t01 =
                fma2(nx[q], xv.x, fma2(ny[q], yv.x, fma2(nz[q], zv.x, wv.x)));
            const unsigned long long t23 =
                fma2(nx[q], xv.y, fma2(ny[q], yv.y, fma2(nz[q], zv.y, wv.y)));
            float u0, u1, u2, u3;
            unpack2(t01, u0, u1); unpack2(t23, u2, u3);
            m0[q] = fminf(m0[q], u0); m1[q] = fminf(m1[q], u1);
            m2[q] = fminf(m2[q], u2); m3[q] = fminf(m3[q], u3);
        }
    }

    // ---- epilogue: atomicMin WITH return; returns prove L2 commit ----
    const int qbase = (dir * BATCH + b) * NPTS;
    int ret[QPT];
    #pragma unroll
    for (int q = 0; q < QPT; q++) {
        const float v = p2[q] + fminf(fminf(m0[q], m1[q]), fminf(m2[q], m3[q]));
        ret[q] = atomicMin(&g_minneg[qbase + iBase + q * TPB], __float_as_int(-v));
    }
    // Dependency anchor: thread cannot pass this until all 4 returns arrived,
    // i.e. all 4 mins are committed at L2. (Condition is effectively never
    // true; the store is just unremovable.)
    const int acc = ret[0] ^ ret[1] ^ ret[2] ^ ret[3];
    if (acc == 0x12345678) s_dummy = acc;
    __syncthreads();                    // whole block's atomics committed

    // ---- last-block finisher (no gpu fence anywhere) ----
    __shared__ unsigned int s_rank;
    if (threadIdx.x == 0) s_rank = atomicAdd(&g_count, 1u);
    __syncthreads();
    if (s_rank != NBLK - 1) return;

    // Acquire via L1-bypass loads: values come straight from L2.
    float s = 0.0f;
    int4* __restrict__ P = (int4*)g_minneg;
    #pragma unroll 4
    for (int k = 0; k < NQ / 4 / TPB; k++) {          // 256 int4 per thread
        const int idx = threadIdx.x + k * TPB;
        const int4 v = __ldcv(&P[idx]);
        s += fmaxf(-__int_as_float(v.x), 0.0f)
           + fmaxf(-__int_as_float(v.y), 0.0f)
           + fmaxf(-__int_as_float(v.z), 0.0f)
           + fmaxf(-__int_as_float(v.w), 0.0f);
        P[idx] = make_int4(0, 0, 0, 0);               // restore identity for replay
    }

    #pragma unroll
    for (int o = 16; o > 0; o >>= 1)
        s += __shfl_down_sync(0xffffffffu, s, o);

    __shared__ float wsum[TPB / 32];
    if ((threadIdx.x & 31) == 0) wsum[threadIdx.x >> 5] = s;
    __syncthreads();
    if (threadIdx.x == 0) {
        out[0] = (wsum[0] + wsum[1]) / (float)(BATCH * NPTS);
        g_count = 0;                                   // reset for next replay
    }
}

extern "C" void kernel_launch(void* const* d_in, const int* in_sizes, int n_in,
                              void* d_out, int out_size)
{
    const float* A  = (const float*)d_in[0];  // coor_recon [8,4096,3]
    const float* Bp = (const float*)d_in[1];  // pc_gd      [8,4096,3]
    float* out = (float*)d_out;

    dim3 grid(ITILES, BATCH, 2 * NSPLIT);     // 2048 blocks, SINGLE launch
    chamfer_kernel<<<grid, TPB>>>(A, Bp, out);
}

// round 13
// speedup vs baseline: 1.3910x; 1.3910x over previous
#include <cuda_runtime.h>

#define BATCH  8
#define NPTS   4096
#define TPB    64
#define QPT    4
#define QPB    (TPB * QPT)       // 256 queries per block
#define ITILES (NPTS / QPB)      // 16
#define NSPLIT 8                 // target splits
#define CHUNK  (NPTS / NSPLIT)   // 512 targets per block (one 8KB smem tile)
#define NJ     (CHUNK / 4)       // 128 j-groups of 4 targets
#define NQ     (2 * BATCH * NPTS)            // 65536 queries
#define SBLK   64
#define STPB   256

// bits of -(min d2) per query, signed-int atomicMin.
// .bss zero (= +0.0 bits) is the identity: any negative int wins. No init.
// sum_kernel re-zeros slots after reading, restoring state for graph replay.
__device__ __align__(16) int g_minneg[NQ];
__device__ float             g_cpart[SBLK];
__device__ unsigned int      g_count;        // zero-init; sum_kernel resets

// ---- packed f32x2 helpers (Blackwell; PTX-only) ----
__device__ __forceinline__ unsigned long long bcast2(float v) {
    unsigned long long r;
    asm("mov.b64 %0, {%1, %1};" : "=l"(r) : "f"(v));
    return r;
}
__device__ __forceinline__ unsigned long long fma2(unsigned long long a,
                                                   unsigned long long b,
                                                   unsigned long long c) {
    unsigned long long d;
    asm("fma.rn.f32x2 %0, %1, %2, %3;" : "=l"(d) : "l"(a), "l"(b), "l"(c));
    return d;
}
__device__ __forceinline__ void unpack2(unsigned long long v, float& lo, float& hi) {
    asm("mov.b64 {%0, %1}, %2;" : "=f"(lo), "=f"(hi) : "l"(v));
}

// grid (ITILES, BATCH, 2*NSPLIT); z: dir = z&1, split = z>>1.
// R10 structure (best measured 47.1us) + software-pipelined smem reads:
// prefetch j-group j+1 into registers while computing group j, hiding the
// 29-cyc LDS latency behind 48 cycles of FFMA2 work per group.
__global__ __launch_bounds__(TPB) void chamfer_kernel(
    const float* __restrict__ A, const float* __restrict__ Bp)
{
    const int dir   = blockIdx.z & 1;
    const int split = blockIdx.z >> 1;
    const int b     = blockIdx.y;
    const float* __restrict__ xb = (dir == 0 ? A : Bp) + (size_t)b * NPTS * 3;
    const float* __restrict__ yb = (dir == 0 ? Bp : A) + (size_t)b * NPTS * 3;

    // +4 pad: the pipelined prologue prefetches one group past the end;
    // those values are never consumed.
    __shared__ __align__(16) float xs[CHUNK + 4], ys[CHUNK + 4],
                                   zs[CHUNK + 4], ws[CHUNK + 4];

    // ---- load the target tile (once per block) ----
    const int t0 = split * CHUNK;
    #pragma unroll
    for (int k = threadIdx.x; k < CHUNK; k += TPB) {
        const float qx = yb[3 * (t0 + k) + 0];
        const float qy = yb[3 * (t0 + k) + 1];
        const float qz = yb[3 * (t0 + k) + 2];
        xs[k] = qx; ys[k] = qy; zs[k] = qz;
        ws[k] = fmaf(qx, qx, fmaf(qy, qy, qz * qz));
    }
    // Deterministic pad fill (first 4 threads)
    if (threadIdx.x < 4) {
        xs[CHUNK + threadIdx.x] = 0.0f; ys[CHUNK + threadIdx.x] = 0.0f;
        zs[CHUNK + threadIdx.x] = 0.0f; ws[CHUNK + threadIdx.x] = 0.0f;
    }

    // ---- load 4 query points, fold -2 into packed broadcasts ----
    const int iBase = blockIdx.x * QPB + threadIdx.x;
    float p2[QPT];
    unsigned long long nx[QPT], ny[QPT], nz[QPT];
    #pragma unroll
    for (int q = 0; q < QPT; q++) {
        const int i = iBase + q * TPB;
        const float px = xb[3 * i + 0];
        const float py = xb[3 * i + 1];
        const float pz = xb[3 * i + 2];
        p2[q] = fmaf(px, px, fmaf(py, py, pz * pz));
        nx[q] = bcast2(-2.0f * px);
        ny[q] = bcast2(-2.0f * py);
        nz[q] = bcast2(-2.0f * pz);
    }

    __syncthreads();

    float m0[QPT], m1[QPT], m2[QPT], m3[QPT];
    #pragma unroll
    for (int q = 0; q < QPT; q++) { m0[q] = m1[q] = m2[q] = m3[q] = 3.0e38f; }

    const ulonglong2* __restrict__ X4 = (const ulonglong2*)xs;
    const ulonglong2* __restrict__ Y4 = (const ulonglong2*)ys;
    const ulonglong2* __restrict__ Z4 = (const ulonglong2*)zs;
    const ulonglong2* __restrict__ W4 = (const ulonglong2*)ws;

    // ---- software-pipelined scan: prefetch j+1 while computing j ----
    ulonglong2 xv = X4[0], yv = Y4[0], zv = Z4[0], wv = W4[0];

    #pragma unroll 4
    for (int j = 0; j < NJ; j++) {
        // prefetch next group (pad makes j = NJ-1 safe; values unused)
        const ulonglong2 xn = X4[j + 1];
        const ulonglong2 yn = Y4[j + 1];
        const ulonglong2 zn = Z4[j + 1];
        const ulonglong2 wn = W4[j + 1];

        #pragma unroll
        for (int q = 0; q < QPT; q++) {
            const unsigned long long t01 =
                fma2(nx[q], xv.x, fma2(ny[q], yv.x, fma2(nz[q], zv.x, wv.x)));
            const unsigned long long t23 =
                fma2(nx[q], xv.y, fma2(ny[q], yv.y, fma2(nz[q], zv.y, wv.y)));
            float u0, u1, u2, u3;
            unpack2(t01, u0, u1); unpack2(t23, u2, u3);
            m0[q] = fminf(m0[q], u0); m1[q] = fminf(m1[q], u1);
            m2[q] = fminf(m2[q], u2); m3[q] = fminf(m3[q], u3);
        }

        xv = xn; yv = yn; zv = zn; wv = wn;
    }

    const int qbase = (dir * BATCH + b) * NPTS;
    #pragma unroll
    for (int q = 0; q < QPT; q++) {
        const float v = p2[q] + fminf(fminf(m0[q], m1[q]), fminf(m2[q], m3[q]));
        atomicMin(&g_minneg[qbase + iBase + q * TPB], __float_as_int(-v));
    }
    // fire-and-forget REDG.MIN; kernel boundary orders them before sum_kernel
}

// Clamp + deterministic mean; re-zeros g_minneg for the next graph replay.
__global__ __launch_bounds__(STPB) void sum_kernel(float* __restrict__ out)
{
    const int t = blockIdx.x * STPB + threadIdx.x;       // 16384 threads
    int4* __restrict__ P = (int4*)g_minneg;
    const int4 v = P[t];
    P[t] = make_int4(0, 0, 0, 0);                        // restore identity
    float s = fmaxf(-__int_as_float(v.x), 0.0f)
            + fmaxf(-__int_as_float(v.y), 0.0f)
            + fmaxf(-__int_as_float(v.z), 0.0f)
            + fmaxf(-__int_as_float(v.w), 0.0f);

    #pragma unroll
    for (int o = 16; o > 0; o >>= 1)
        s += __shfl_down_sync(0xffffffffu, s, o);

    __shared__ float wsum[STPB / 32];
    __shared__ int   is_last;
    if ((threadIdx.x & 31) == 0) wsum[threadIdx.x >> 5] = s;
    __syncthreads();

    if (threadIdx.x == 0) {
        float ps = 0.0f;
        #pragma unroll
        for (int w = 0; w < STPB / 32; w++) ps += wsum[w];
        g_cpart[blockIdx.x] = ps;
        __threadfence();
        unsigned int old = atomicAdd(&g_count, 1u);
        is_last = (old == SBLK - 1) ? 1 : 0;
    }
    __syncthreads();

    if (is_last && threadIdx.x < 32) {
        float v2 = g_cpart[threadIdx.x] + g_cpart[threadIdx.x + 32];
        #pragma unroll
        for (int o = 16; o > 0; o >>= 1)
            v2 += __shfl_down_sync(0xffffffffu, v2, o);
        if (threadIdx.x == 0) {
            out[0] = v2 / (float)(BATCH * NPTS);
            g_count = 0;                                  // reset for next replay
        }
    }
}

extern "C" void kernel_launch(void* const* d_in, const int* in_sizes, int n_in,
                              void* d_out, int out_size)
{
    const float* A  = (const float*)d_in[0];  // coor_recon [8,4096,3]
    const float* Bp = (const float*)d_in[1];  // pc_gd      [8,4096,3]
    float* out = (float*)d_out;

    dim3 grid(ITILES, BATCH, 2 * NSPLIT);     // 2048 blocks
    chamfer_kernel<<<grid, TPB>>>(A, Bp);
    sum_kernel<<<SBLK, STPB>>>(out);
}